// round 4
// baseline (speedup 1.0000x reference)
#include <cuda_runtime.h>
#include <cuda_bf16.h>

// FastSpeech2 hard duration-based frame->token scalar averaging.
// Inputs (metadata order):
//   d_in[0] frame_scalar      float32 [B, 8192]
//   d_in[1] duration          float32 [B, 1024]
//   d_in[2] frame_scalar_len  int32   [B]
//   d_in[3] duration_len      int32   [B]
// Output: token_scalar float32 [B, 1024] (+ optional duration_len as f32 [B]
// if the harness concatenates the tuple outputs).

#define TFR 8192
#define TTK 1024
#define NTHREADS 256
#define CHF (TFR / NTHREADS)   // 32 frame elements per thread
#define CHF4 (CHF / 4)         // 8 float4 loads per thread
#define CHT (TTK / NTHREADS)   // 4 token elements per thread
#define NWARPS (NTHREADS / 32)

// Padded smem addressing: one extra slot every 32 floats -> conflict-free for
// both striped writes and per-thread contiguous-chunk reads.
__device__ __forceinline__ int PAD(int i) { return i + (i >> 5); }
#define CFS_SLOTS (TFR - 1 + ((TFR - 1) >> 5) + 1)   // PAD(8191)+1 = 8447

__global__ __launch_bounds__(NTHREADS)
void fs2_dur_avg_kernel(const float* __restrict__ frame_scalar,
                        const float* __restrict__ duration,
                        const int*   __restrict__ frame_scalar_len,
                        const int*   __restrict__ duration_len,
                        float*       __restrict__ out,
                        int B, int write_extra)
{
    __shared__ float s_cfs[CFS_SLOTS];      // inclusive prefix sums of frame row
    __shared__ float s_wsum[NWARPS];
    __shared__ float s_woff[NWARPS];

    const int row  = blockIdx.x;
    const int tid  = threadIdx.x;
    const int lane = tid & 31;
    const int wid  = tid >> 5;

    // ---------------- Phase 1: frame_scalar prefix sum ----------------
    // Vector (float4) coalesced global loads; scalar padded smem stores.
    {
        const float4* fs4 = reinterpret_cast<const float4*>(
            frame_scalar + (size_t)row * TFR);
        #pragma unroll
        for (int k = 0; k < CHF4; k++) {
            const int v4idx = tid + k * NTHREADS;     // coalesced 512B/warp
            const float4 w = fs4[v4idx];
            const int fidx = v4idx * 4;
            s_cfs[PAD(fidx + 0)] = w.x;
            s_cfs[PAD(fidx + 1)] = w.y;
            s_cfs[PAD(fidx + 2)] = w.z;
            s_cfs[PAD(fidx + 3)] = w.w;
        }
    }
    __syncthreads();

    // Per-thread contiguous chunk -> registers, local inclusive scan.
    float v[CHF];
    {
        const int base = tid * CHF;
        float run = 0.0f;
        #pragma unroll
        for (int k = 0; k < CHF; k++) {
            run += s_cfs[PAD(base + k)];         // conflict-free (bank = (tid+k)%32)
            v[k] = run;
        }
        // Block scan of per-thread totals.
        float tot = run;
        float incl = tot;
        #pragma unroll
        for (int d = 1; d < 32; d <<= 1) {
            float t = __shfl_up_sync(0xffffffffu, incl, d);
            if (lane >= d) incl += t;
        }
        if (lane == 31) s_wsum[wid] = incl;
        __syncthreads();
        if (tid == 0) {
            float acc = 0.0f;
            #pragma unroll
            for (int w = 0; w < NWARPS; w++) { s_woff[w] = acc; acc += s_wsum[w]; }
        }
        __syncthreads();
        const float off = s_woff[wid] + (incl - tot);   // exclusive offset of this chunk
        #pragma unroll
        for (int k = 0; k < CHF; k++)
            s_cfs[PAD(base + k)] = v[k] + off;          // write own chunk back (no hazard)
    }
    __syncthreads();
    // Now s_cfs[PAD(i)] = sum(frame_scalar[row, 0..i]) inclusive.
    // cfs(e) := sum over [0, e) = (e == 0) ? 0 : s_cfs[PAD(e-1)].

    // ---------------- Phase 2: token durations + gather ----------------
    const int   dl = duration_len[row];
    const float fl = (float)frame_scalar_len[row];

    const float4 d4 = reinterpret_cast<const float4*>(duration + (size_t)row * TTK)[tid];
    float dv[CHT];
    {
        const float din[CHT] = {d4.x, d4.y, d4.z, d4.w};
        const int jbase = tid * CHT;
        #pragma unroll
        for (int k = 0; k < CHT; k++) {
            // round half-to-even (matches jnp.round), clamp >= 0, zero past dlen
            float r = fmaxf(rintf(din[k]), 0.0f);
            dv[k] = (jbase + k < dl) ? r : 0.0f;
        }
    }
    // Local inclusive cumsum of durations (exact: small-integer sums).
    float p[CHT];
    {
        float run = 0.0f;
        #pragma unroll
        for (int k = 0; k < CHT; k++) { run += dv[k]; p[k] = run; }
        float tot = run;
        float incl = tot;
        #pragma unroll
        for (int d = 1; d < 32; d <<= 1) {
            float t = __shfl_up_sync(0xffffffffu, incl, d);
            if (lane >= d) incl += t;
        }
        if (lane == 31) s_wsum[wid] = incl;
        __syncthreads();
        if (tid == 0) {
            float acc = 0.0f;
            #pragma unroll
            for (int w = 0; w < NWARPS; w++) { s_woff[w] = acc; acc += s_wsum[w]; }
        }
        __syncthreads();
        const float off = s_woff[wid] + (incl - tot);

        float4 res;
        float* rp = reinterpret_cast<float*>(&res);
        #pragma unroll
        for (int k = 0; k < CHT; k++) {
            const float cend_raw   = off + p[k];         // cumsum through token j
            const float cstart_raw = cend_raw - dv[k];   // cumsum through token j-1
            const float endf   = fminf(cend_raw, fl);
            const float startf = fminf(cstart_raw, fl);
            const float dlen_f = endf - startf;          // exact integer-valued float
            const int e = (int)endf;
            const int s = (int)startf;
            const float cfs_e = (e == 0) ? 0.0f : s_cfs[PAD(e - 1)];
            const float cfs_s = (s == 0) ? 0.0f : s_cfs[PAD(s - 1)];
            const float seg = cfs_e - cfs_s;
            rp[k] = (dlen_f > 0.0f) ? seg / fmaxf(dlen_f, 1.0f) : 0.0f;
        }
        reinterpret_cast<float4*>(out + (size_t)row * TTK)[tid] = res;
    }

    // Optional second tuple output: duration_len (numeric cast to f32).
    if (write_extra && tid == 0)
        out[(size_t)B * TTK + row] = (float)dl;
}

extern "C" void kernel_launch(void* const* d_in, const int* in_sizes, int n_in,
                              void* d_out, int out_size) {
    const float* frame_scalar     = (const float*)d_in[0];
    const float* duration         = (const float*)d_in[1];
    const int*   frame_scalar_len = (const int*)d_in[2];
    const int*   duration_len     = (const int*)d_in[3];
    float* out = (float*)d_out;

    const int B = in_sizes[2];                       // [B] int32
    const int write_extra = (out_size > B * TTK) ? 1 : 0;

    fs2_dur_avg_kernel<<<B, NTHREADS>>>(frame_scalar, duration,
                                        frame_scalar_len, duration_len,
                                        out, B, write_extra);
}

// round 5
// speedup vs baseline: 1.0289x; 1.0289x over previous
#include <cuda_runtime.h>
#include <cuda_bf16.h>

// FastSpeech2 hard duration-based frame->token scalar averaging.
// Inputs (metadata order):
//   d_in[0] frame_scalar      float32 [B, 8192]
//   d_in[1] duration          float32 [B, 1024]
//   d_in[2] frame_scalar_len  int32   [B]
//   d_in[3] duration_len      int32   [B]
// Output: token_scalar float32 [B, 1024] (+ optional duration_len as f32 [B]).
//
// R4 change: deferred-offset scan. Local chunk prefixes live in smem; the
// block-level chunk offsets live in a 256-entry side table added at gather
// time. This kills the v[32] register array (regs 64 -> ~40), letting
// __launch_bounds__(256,6) reach 6 CTAs/SM (smem-bound) instead of 4
// (register-bound), to raise cross-CTA HBM overlap.

#define TFR 8192
#define TTK 1024
#define NTHREADS 256
#define CHF (TFR / NTHREADS)   // 32 frame elements per thread
#define CHF4 (CHF / 4)         // 8 float4 loads per thread
#define CHT (TTK / NTHREADS)   // 4 token elements per thread
#define NWARPS (NTHREADS / 32)

// Padded smem addressing: one extra slot every 32 floats -> conflict-free for
// both striped writes and per-thread contiguous-chunk reads.
__device__ __forceinline__ int PAD(int i) { return i + (i >> 5); }
#define CFS_SLOTS (TFR - 1 + ((TFR - 1) >> 5) + 1)   // PAD(8191)+1 = 8447

__global__ __launch_bounds__(NTHREADS, 6)
void fs2_dur_avg_kernel(const float* __restrict__ frame_scalar,
                        const float* __restrict__ duration,
                        const int*   __restrict__ frame_scalar_len,
                        const int*   __restrict__ duration_len,
                        float*       __restrict__ out,
                        int B, int write_extra)
{
    __shared__ float s_cfs[CFS_SLOTS];   // local (per-chunk) inclusive prefixes
    __shared__ float s_toff[NTHREADS];   // exclusive offset of each thread chunk
    __shared__ float s_wsum[NWARPS];
    __shared__ float s_woff[NWARPS];

    const int row  = blockIdx.x;
    const int tid  = threadIdx.x;
    const int lane = tid & 31;
    const int wid  = tid >> 5;

    // ---------------- Phase 1: stage frame row (coalesced float4) ----------
    {
        const float4* fs4 = reinterpret_cast<const float4*>(
            frame_scalar + (size_t)row * TFR);
        #pragma unroll
        for (int k = 0; k < CHF4; k++) {
            const int v4idx = tid + k * NTHREADS;     // coalesced 512B/warp
            const float4 w = fs4[v4idx];
            const int fidx = v4idx * 4;
            s_cfs[PAD(fidx + 0)] = w.x;
            s_cfs[PAD(fidx + 1)] = w.y;
            s_cfs[PAD(fidx + 2)] = w.z;
            s_cfs[PAD(fidx + 3)] = w.w;
        }
    }
    __syncthreads();

    // ---------------- Phase 2: local prefix in place + chunk-offset table ---
    {
        const int base = tid * CHF;
        float run = 0.0f;
        #pragma unroll
        for (int k = 0; k < CHF; k++) {
            const int i = PAD(base + k);             // conflict-free (bank=(tid+k)%32)
            run += s_cfs[i];
            s_cfs[i] = run;                          // local inclusive prefix
        }
        // Block scan of per-thread chunk totals.
        const float tot = run;
        float incl = tot;
        #pragma unroll
        for (int d = 1; d < 32; d <<= 1) {
            float t = __shfl_up_sync(0xffffffffu, incl, d);
            if (lane >= d) incl += t;
        }
        if (lane == 31) s_wsum[wid] = incl;
        __syncthreads();
        if (tid == 0) {
            float acc = 0.0f;
            #pragma unroll
            for (int w = 0; w < NWARPS; w++) { s_woff[w] = acc; acc += s_wsum[w]; }
        }
        __syncthreads();
        s_toff[tid] = s_woff[wid] + (incl - tot);    // exclusive offset of chunk tid
    }
    __syncthreads();
    // Now cfs(e) := sum frame_scalar[row, 0..e) =
    //   (e == 0) ? 0 : s_cfs[PAD(e-1)] + s_toff[(e-1) >> 5].

    // ---------------- Phase 3: token durations + gather ----------------
    const int   dl = duration_len[row];
    const float fl = (float)frame_scalar_len[row];

    const float4 d4 = reinterpret_cast<const float4*>(duration + (size_t)row * TTK)[tid];
    float dv[CHT];
    {
        const float din[CHT] = {d4.x, d4.y, d4.z, d4.w};
        const int jbase = tid * CHT;
        #pragma unroll
        for (int k = 0; k < CHT; k++) {
            // round half-to-even (matches jnp.round), clamp >= 0, zero past dlen
            float r = fmaxf(rintf(din[k]), 0.0f);
            dv[k] = (jbase + k < dl) ? r : 0.0f;
        }
    }
    // Local inclusive cumsum of durations (exact: small-integer sums).
    {
        float p[CHT];
        float run = 0.0f;
        #pragma unroll
        for (int k = 0; k < CHT; k++) { run += dv[k]; p[k] = run; }
        const float tot = run;
        float incl = tot;
        #pragma unroll
        for (int d = 1; d < 32; d <<= 1) {
            float t = __shfl_up_sync(0xffffffffu, incl, d);
            if (lane >= d) incl += t;
        }
        if (lane == 31) s_wsum[wid] = incl;
        __syncthreads();
        if (tid == 0) {
            float acc = 0.0f;
            #pragma unroll
            for (int w = 0; w < NWARPS; w++) { s_woff[w] = acc; acc += s_wsum[w]; }
        }
        __syncthreads();
        const float off = s_woff[wid] + (incl - tot);

        float4 res;
        float* rp = reinterpret_cast<float*>(&res);
        #pragma unroll
        for (int k = 0; k < CHT; k++) {
            const float cend_raw   = off + p[k];         // cumsum through token j
            const float cstart_raw = cend_raw - dv[k];   // cumsum through token j-1
            const float endf   = fminf(cend_raw, fl);
            const float startf = fminf(cstart_raw, fl);
            const float dlen_f = endf - startf;          // exact integer-valued float
            const int e = (int)endf;
            const int s = (int)startf;
            const float cfs_e = (e == 0) ? 0.0f
                               : s_cfs[PAD(e - 1)] + s_toff[(e - 1) >> 5];
            const float cfs_s = (s == 0) ? 0.0f
                               : s_cfs[PAD(s - 1)] + s_toff[(s - 1) >> 5];
            const float seg = cfs_e - cfs_s;
            rp[k] = (dlen_f > 0.0f) ? seg / fmaxf(dlen_f, 1.0f) : 0.0f;
        }
        reinterpret_cast<float4*>(out + (size_t)row * TTK)[tid] = res;
    }

    // Optional second tuple output: duration_len (numeric cast to f32).
    if (write_extra && tid == 0)
        out[(size_t)B * TTK + row] = (float)dl;
}

extern "C" void kernel_launch(void* const* d_in, const int* in_sizes, int n_in,
                              void* d_out, int out_size) {
    const float* frame_scalar     = (const float*)d_in[0];
    const float* duration         = (const float*)d_in[1];
    const int*   frame_scalar_len = (const int*)d_in[2];
    const int*   duration_len     = (const int*)d_in[3];
    float* out = (float*)d_out;

    const int B = in_sizes[2];                       // [B] int32
    const int write_extra = (out_size > B * TTK) ? 1 : 0;

    fs2_dur_avg_kernel<<<B, NTHREADS>>>(frame_scalar, duration,
                                        frame_scalar_len, duration_len,
                                        out, B, write_extra);
}